// round 11
// baseline (speedup 1.0000x reference)
#include <cuda_runtime.h>
#include <mma.h>

using namespace nvcuda;

#define NN 50000
#define NE 800000
#define IN_CH 64

// ---------------------------------------------------------------------------
// Scratch layout (single __device__ array). Only [0, ZERO_CNT) is memset per
// launch (flag + degree histogram). All offsets are multiples of 4 floats.
// ---------------------------------------------------------------------------
constexpr size_t OFF_FLAG   = 0;                               // [4] int
constexpr size_t OFF_DEGI   = OFF_FLAG + 4;                    // [NN] int
constexpr size_t ZERO_CNT   = OFF_DEGI + NN;                   // zeroed region end
constexpr size_t OFF_EXCL   = ZERO_CNT;                        // [NN] int
constexpr size_t OFF_BSUM   = OFF_EXCL + NN;                   // [256] int
constexpr size_t OFF_OFFS   = OFF_BSUM + 256;                  // [NN+16] int
constexpr size_t OFF_CURS   = OFF_OFFS + NN + 16;              // [NN] int
constexpr size_t OFF_EIDX   = OFF_CURS + NN;                   // [2*NE] int (src|dst)
constexpr size_t OFF_CSR    = OFF_EIDX + (size_t)2 * NE;       // [NE] int
constexpr size_t OFF_AGGX   = OFF_CSR  + NE;                   // [NN*64] float
constexpr size_t OFF_H1     = OFF_AGGX + (size_t)NN * 64;      // [NN*256]
constexpr size_t OFF_T1     = OFF_H1   + (size_t)NN * 256;     // [NN*256]
constexpr size_t OFF_Q2     = OFF_T1   + (size_t)NN * 256;     // [NN*256] rel|root
constexpr size_t OFF_H2     = OFF_Q2   + (size_t)NN * 256;     // [NN*128]
constexpr size_t OFF_Q3     = OFF_H2   + (size_t)NN * 128;     // [NN*64] rel|root
constexpr size_t OFF_W2CAT  = OFF_Q3   + (size_t)NN * 64;      // [256*256]
constexpr size_t OFF_B2CAT  = OFF_W2CAT + 256 * 256;           // [256]
constexpr size_t OFF_W3CAT  = OFF_B2CAT + 256;                 // [128*64]
constexpr size_t OFF_B3CAT  = OFF_W3CAT + 128 * 64;            // [64]
constexpr size_t TOTAL_F    = OFF_B3CAT + 64;

__device__ __align__(128) float g_scratch[TOTAL_F];

// ---------------------------------------------------------------------------
// Edge-index dtype detection + conversion (clamped to [0, NN) for safety).
// Fused degree histogram: dst-half threads bump degi while converting.
// ---------------------------------------------------------------------------
__global__ void detect_kernel(const unsigned int* __restrict__ raw, int* __restrict__ flag) {
    int t = threadIdx.x;
    unsigned int v = 0;
    for (int i = t; i < 512; i += blockDim.x) v |= raw[2 * i + 1];
    if (__syncthreads_or(v != 0) && t == 0) *flag = 1;
}

__global__ void convert_hist_kernel(const void* __restrict__ raw, const int* __restrict__ flag,
                                    int* __restrict__ eidx, int* __restrict__ degi) {
    int i = blockIdx.x * blockDim.x + threadIdx.x;
    if (i < 2 * NE) {
        int v = (*flag) ? ((const int*)raw)[i]
                        : (int)((const long long*)raw)[i];
        v = min(max(v, 0), NN - 1);
        eidx[i] = v;
        if (i >= NE) atomicAdd(&degi[v], 1);   // dst half -> degree histogram
    }
}

// ---------------------------------------------------------------------------
// CSR construction: exclusive scan (3 small kernels) -> bucket scatter
// ---------------------------------------------------------------------------
__global__ void scan1_kernel(const int* __restrict__ degi, int* __restrict__ excl,
                             int* __restrict__ bsum) {
    __shared__ int sm[256];
    int t = threadIdx.x;
    int i = blockIdx.x * 256 + t;
    int v = (i < NN) ? degi[i] : 0;
    sm[t] = v;
    __syncthreads();
    for (int off = 1; off < 256; off <<= 1) {
        int x = (t >= off) ? sm[t - off] : 0;
        __syncthreads();
        sm[t] += x;
        __syncthreads();
    }
    if (i < NN) excl[i] = sm[t] - v;
    if (t == 255) bsum[blockIdx.x] = sm[255];
}

__global__ void scan2_kernel(int* __restrict__ bsum, int nb) {
    __shared__ int sm[256];
    int t = threadIdx.x;
    int v = (t < nb) ? bsum[t] : 0;
    sm[t] = v;
    __syncthreads();
    for (int off = 1; off < 256; off <<= 1) {
        int x = (t >= off) ? sm[t - off] : 0;
        __syncthreads();
        sm[t] += x;
        __syncthreads();
    }
    if (t < nb) bsum[t] = sm[t] - v;   // exclusive
}

__global__ void scan3_kernel(const int* __restrict__ excl, const int* __restrict__ bsum,
                             int* __restrict__ offs, int* __restrict__ curs) {
    int i = blockIdx.x * blockDim.x + threadIdx.x;
    if (i < NN) {
        int o = excl[i] + bsum[i >> 8];
        offs[i] = o;
        curs[i] = o;
    }
    if (i == 0) offs[NN] = NE;
}

__global__ void csr_build_kernel(const int* __restrict__ esrc, const int* __restrict__ edst,
                                 int* __restrict__ curs, int* __restrict__ csr) {
    int e = blockIdx.x * blockDim.x + threadIdx.x;
    if (e < NE) {
        int p = atomicAdd(&curs[edst[e]], 1);
        csr[p] = esrc[e];
    }
}

// ---------------------------------------------------------------------------
// Segmented mean-aggregation: one warp per destination node, 4-edge unroll.
// P rows have stride LDP (cols [0,D) are the rel projection); T (stride LDP)
// is the root-path result to add. SPLIT: D=32 mu/logstd split store.
// ---------------------------------------------------------------------------
template <int D, int LDP, bool HAS_ADD, bool RELU, bool SPLIT>
__global__ void agg_kernel(const int* __restrict__ offs, const int* __restrict__ csr,
                           const float* __restrict__ P, const float* __restrict__ T,
                           float* __restrict__ OUT) {
    constexpr int R = D / 32;
    int w = (blockIdx.x * blockDim.x + threadIdx.x) >> 5;
    int lane = threadIdx.x & 31;
    if (w >= NN) return;
    int s = offs[w], e = offs[w + 1];
    float acc[R] = {};
    int i = s;
    for (; i + 3 < e; i += 4) {
        const float* r0 = P + (size_t)csr[i] * LDP;
        const float* r1 = P + (size_t)csr[i + 1] * LDP;
        const float* r2 = P + (size_t)csr[i + 2] * LDP;
        const float* r3 = P + (size_t)csr[i + 3] * LDP;
#pragma unroll
        for (int r = 0; r < R; r++)
            acc[r] += (__ldg(r0 + lane + 32 * r) + __ldg(r1 + lane + 32 * r))
                    + (__ldg(r2 + lane + 32 * r) + __ldg(r3 + lane + 32 * r));
    }
    for (; i < e; i++) {
        const float* r0 = P + (size_t)csr[i] * LDP;
#pragma unroll
        for (int r = 0; r < R; r++) acc[r] += __ldg(r0 + lane + 32 * r);
    }
    int deg = e - s;
    float sc = deg > 0 ? 1.0f / (float)deg : 0.0f;
#pragma unroll
    for (int r = 0; r < R; r++) {
        int col = lane + 32 * r;
        float v = acc[r] * sc;
        if (HAS_ADD) v += T[(size_t)w * LDP + col];
        if (RELU) v = fmaxf(v, 0.f);
        if (SPLIT) {
            float* p = (col < 16) ? (OUT + (size_t)w * 16 + col)
                                  : (OUT + (size_t)NN * 16 + (size_t)w * 16 + (col - 16));
            *p = v;
        } else {
            OUT[(size_t)w * D + col] = v;
        }
    }
}

// ---------------------------------------------------------------------------
// Pack concatenated weights: W2cat [256,256] = [W2_rel | W2_root],
// b2cat = [0|b2]; W3cat [128,64] = [Wmu_rel|Wls_rel|Wmu_root|Wls_root],
// b3cat = [0|bmu|bls].
// ---------------------------------------------------------------------------
__global__ void pack_kernel(const float* __restrict__ W2_rel, const float* __restrict__ W2_root,
                            const float* __restrict__ b2,
                            const float* __restrict__ Wmu_rel, const float* __restrict__ Wls_rel,
                            const float* __restrict__ Wmu_root, const float* __restrict__ Wls_root,
                            const float* __restrict__ bmu, const float* __restrict__ bls,
                            float* __restrict__ W2cat, float* __restrict__ b2cat,
                            float* __restrict__ W3cat, float* __restrict__ b3cat) {
    int i = blockIdx.x * blockDim.x + threadIdx.x;
    if (i < 256 * 256) {
        int k = i >> 8, n = i & 255;
        W2cat[i] = (n < 128) ? W2_rel[k * 128 + n] : W2_root[k * 128 + (n - 128)];
    }
    if (i < 128 * 64) {
        int k = i >> 6, n = i & 63;
        float v;
        if (n < 16)      v = Wmu_rel[k * 16 + n];
        else if (n < 32) v = Wls_rel[k * 16 + (n - 16)];
        else if (n < 48) v = Wmu_root[k * 16 + (n - 32)];
        else             v = Wls_root[k * 16 + (n - 48)];
        W3cat[i] = v;
    }
    if (i < 256) b2cat[i] = (i < 128) ? 0.f : b2[i - 128];
    if (i < 64)  b3cat[i] = (i < 32) ? 0.f : ((i < 48) ? bmu[i - 32] : bls[i - 48]);
}

// ---------------------------------------------------------------------------
// tf32 wmma GEMM: 128xBN block tile, BK=16, warps 4 x (BN/32), each warp
// 32x32 (2x2 m16n16k8 fragments), fp32 accumulate. tf32 convert at smem store.
// HAS_ADD: epilogue += ADD[m,n] (stride N); bias added if non-null; RELU.
// ---------------------------------------------------------------------------
template <int BN, bool HAS_ADD, bool RELU>
__global__ __launch_bounds__(32 * 4 * (BN / 32))
void mm_kernel(const float* __restrict__ A, const float* __restrict__ W,
               const float* __restrict__ ADD,
               const float* __restrict__ bias, float* __restrict__ OUT,
               int M, int K, int N) {
    constexpr int BM = 128, BK = 16;
    constexpr int WN = BN / 32;
    constexpr int NT = 128 * WN;
    constexpr int LDA = BK + 8;
    constexpr int LDB = BN + 8;
    constexpr int LDC = BN + 8;
    constexpr int SZ_AB = BM * LDA + BK * LDB;
    constexpr int SZ_C  = BM * LDC;
    constexpr int SMEM_FLOATS = SZ_AB > SZ_C ? SZ_AB : SZ_C;
    __shared__ __align__(16) float smem[SMEM_FLOATS];
    float* As = smem;
    float* Bs = smem + BM * LDA;
    float* Cs = smem;

    int t    = threadIdx.x;
    int warp = t >> 5;
    int wm   = warp & 3;
    int wn   = warp >> 2;
    int m0   = blockIdx.x * BM;
    int n0   = blockIdx.y * BN;

    wmma::fragment<wmma::accumulator, 16, 16, 8, float> c[2][2];
#pragma unroll
    for (int i = 0; i < 2; i++)
#pragma unroll
        for (int j = 0; j < 2; j++) wmma::fill_fragment(c[i][j], 0.0f);

    for (int k0 = 0; k0 < K; k0 += BK) {
        for (int i = t; i < BM * BK / 4; i += NT) {
            int row = i / (BK / 4);
            int c4  = i % (BK / 4);
            float4 v = make_float4(0.f, 0.f, 0.f, 0.f);
            int m = m0 + row;
            if (m < M) v = *(const float4*)(A + (size_t)m * K + k0 + c4 * 4);
            float* d = As + row * LDA + c4 * 4;
            d[0] = wmma::__float_to_tf32(v.x);
            d[1] = wmma::__float_to_tf32(v.y);
            d[2] = wmma::__float_to_tf32(v.z);
            d[3] = wmma::__float_to_tf32(v.w);
        }
        for (int i = t; i < BK * BN / 4; i += NT) {
            int row = i / (BN / 4);
            int c4  = i % (BN / 4);
            float4 v = *(const float4*)(W + (size_t)(k0 + row) * N + n0 + c4 * 4);
            float* d = Bs + row * LDB + c4 * 4;
            d[0] = wmma::__float_to_tf32(v.x);
            d[1] = wmma::__float_to_tf32(v.y);
            d[2] = wmma::__float_to_tf32(v.z);
            d[3] = wmma::__float_to_tf32(v.w);
        }
        __syncthreads();
#pragma unroll
        for (int kk = 0; kk < BK; kk += 8) {
            wmma::fragment<wmma::matrix_a, 16, 16, 8, wmma::precision::tf32, wmma::row_major> a[2];
            wmma::fragment<wmma::matrix_b, 16, 16, 8, wmma::precision::tf32, wmma::row_major> b[2];
#pragma unroll
            for (int i = 0; i < 2; i++)
                wmma::load_matrix_sync(a[i], As + (wm * 32 + i * 16) * LDA + kk, LDA);
#pragma unroll
            for (int j = 0; j < 2; j++)
                wmma::load_matrix_sync(b[j], Bs + kk * LDB + wn * 32 + j * 16, LDB);
#pragma unroll
            for (int i = 0; i < 2; i++)
#pragma unroll
                for (int j = 0; j < 2; j++)
                    wmma::mma_sync(c[i][j], a[i], b[j], c[i][j]);
        }
        __syncthreads();
    }

#pragma unroll
    for (int i = 0; i < 2; i++)
#pragma unroll
        for (int j = 0; j < 2; j++)
            wmma::store_matrix_sync(Cs + (wm * 32 + i * 16) * LDC + wn * 32 + j * 16,
                                    c[i][j], LDC, wmma::mem_row_major);
    __syncthreads();

    for (int i = t; i < BM * BN / 4; i += NT) {
        int row = i / (BN / 4);
        int c4  = i % (BN / 4);
        int m = m0 + row;
        if (m >= M) continue;
        float4 v = *(float4*)(Cs + row * LDC + c4 * 4);
        int n = n0 + c4 * 4;
        if (bias) {
            v.x += bias[n + 0]; v.y += bias[n + 1];
            v.z += bias[n + 2]; v.w += bias[n + 3];
        }
        if (HAS_ADD) {
            const float4 av = *(const float4*)(ADD + (size_t)m * N + n);
            v.x += av.x; v.y += av.y; v.z += av.z; v.w += av.w;
        }
        if (RELU) {
            v.x = fmaxf(v.x, 0.f); v.y = fmaxf(v.y, 0.f);
            v.z = fmaxf(v.z, 0.f); v.w = fmaxf(v.w, 0.f);
        }
        *(float4*)(OUT + (size_t)m * N + n) = v;
    }
}

// ---------------------------------------------------------------------------
// Launch: s2 runs the edge-independent prologue (pack + x@W1_root) while s0
// builds CSR; after layer-1 combine everything proceeds on s0.
// ---------------------------------------------------------------------------
extern "C" void kernel_launch(void* const* d_in, const int* in_sizes, int n_in,
                              void* d_out, int out_size) {
    const float *x, *W1_rel, *b1, *W1_root, *W2_rel, *b2, *W2_root;
    const float *Wmu_rel, *bmu, *Wmu_root, *Wls_rel, *bls, *Wls_root;
    const void* ei_raw;

    if (in_sizes[0] == NN * IN_CH) {
        // dict order
        x        = (const float*)d_in[0];
        W1_rel   = (const float*)d_in[1];
        b1       = (const float*)d_in[2];
        W1_root  = (const float*)d_in[3];
        W2_rel   = (const float*)d_in[4];
        b2       = (const float*)d_in[5];
        W2_root  = (const float*)d_in[6];
        Wmu_rel  = (const float*)d_in[7];
        bmu      = (const float*)d_in[8];
        Wmu_root = (const float*)d_in[9];
        Wls_rel  = (const float*)d_in[10];
        bls      = (const float*)d_in[11];
        Wls_root = (const float*)d_in[12];
        ei_raw   = d_in[13];
    } else {
        // alphabetical order
        W1_rel   = (const float*)d_in[0];
        W1_root  = (const float*)d_in[1];
        W2_rel   = (const float*)d_in[2];
        W2_root  = (const float*)d_in[3];
        Wls_rel  = (const float*)d_in[4];
        Wls_root = (const float*)d_in[5];
        Wmu_rel  = (const float*)d_in[6];
        Wmu_root = (const float*)d_in[7];
        b1       = (const float*)d_in[8];
        b2       = (const float*)d_in[9];
        bls      = (const float*)d_in[10];
        bmu      = (const float*)d_in[11];
        ei_raw   = d_in[12];
        x        = (const float*)d_in[13];
    }
    float* out = (float*)d_out;

    float* base = nullptr;
    cudaGetSymbolAddress((void**)&base, g_scratch);
    int*   flag   = (int*)(base + OFF_FLAG);
    int*   degi   = (int*)(base + OFF_DEGI);
    int*   excl   = (int*)(base + OFF_EXCL);
    int*   bsum   = (int*)(base + OFF_BSUM);
    int*   offs   = (int*)(base + OFF_OFFS);
    int*   curs   = (int*)(base + OFF_CURS);
    int*   eidx   = (int*)(base + OFF_EIDX);
    int*   csr    = (int*)(base + OFF_CSR);
    int*   esrc   = eidx;
    int*   edst   = eidx + NE;
    float* aggx   = base + OFF_AGGX;
    float* h1     = base + OFF_H1;
    float* t1     = base + OFF_T1;
    float* q2     = base + OFF_Q2;
    float* h2     = base + OFF_H2;
    float* q3     = base + OFF_Q3;
    float* W2cat  = base + OFF_W2CAT;
    float* b2cat  = base + OFF_B2CAT;
    float* W3cat  = base + OFF_W3CAT;
    float* b3cat  = base + OFF_B3CAT;

    // One-time stream/event creation (outside capture on the correctness run;
    // reused identically on every call -> deterministic work).
    static cudaStream_t s2 = nullptr;
    static cudaEvent_t evRoot, evT1;
    if (!s2) {
        cudaStreamCreateWithFlags(&s2, cudaStreamNonBlocking);
        cudaEventCreateWithFlags(&evRoot, cudaEventDisableTiming);
        cudaEventCreateWithFlags(&evT1, cudaEventDisableTiming);
    }
    cudaStream_t s0 = 0;

    const int MB = (NN + 127) / 128;     // 391
    const int AGG_BLOCKS = (NN + 7) / 8; // 8 warps/block
    const int NB = (NN + 255) / 256;     // 196

    // fork s2 off the capture stream
    cudaEventRecord(evRoot, s0);
    cudaStreamWaitEvent(s2, evRoot, 0);

    // ---- s2: edge-independent prologue ----
    pack_kernel<<<(256 * 256 + 255) / 256, 256, 0, s2>>>(
        W2_rel, W2_root, b2, Wmu_rel, Wls_rel, Wmu_root, Wls_root, bmu, bls,
        W2cat, b2cat, W3cat, b3cat);
    mm_kernel<64, false, false><<<dim3(MB, 4), 256, 0, s2>>>(
        x, W1_root, nullptr, b1, t1, NN, 64, 256);          // t1 = x@W1_root + b1
    cudaEventRecord(evT1, s2);

    // ---- s0: edge path (CSR build + aggx) ----
    cudaMemsetAsync(base, 0, ZERO_CNT * sizeof(float), s0);
    detect_kernel<<<1, 256, 0, s0>>>((const unsigned int*)ei_raw, flag);
    convert_hist_kernel<<<(2 * NE + 255) / 256, 256, 0, s0>>>(ei_raw, flag, eidx, degi);
    scan1_kernel<<<NB, 256, 0, s0>>>(degi, excl, bsum);
    scan2_kernel<<<1, 256, 0, s0>>>(bsum, NB);
    scan3_kernel<<<NB, 256, 0, s0>>>(excl, bsum, offs, curs);
    csr_build_kernel<<<(NE + 255) / 256, 256, 0, s0>>>(esrc, edst, curs, csr);
    agg_kernel<64, 64, false, false, false><<<AGG_BLOCKS, 256, 0, s0>>>(
        offs, csr, x, nullptr, aggx);

    // ---- layer 1 combine: h1 = relu(aggx@W1_rel + t1) ----
    cudaStreamWaitEvent(s0, evT1, 0);
    mm_kernel<64, true, true><<<dim3(MB, 4), 256, 0, s0>>>(
        aggx, W1_rel, t1, nullptr, h1, NN, 64, 256);

    // ---- layer 2: q2 = h1@[W2_rel|W2_root] + [0|b2]; h2 = relu(agg+root) ----
    mm_kernel<64, false, false><<<dim3(MB, 4), 256, 0, s0>>>(
        h1, W2cat, nullptr, b2cat, q2, NN, 256, 256);
    agg_kernel<128, 256, true, true, false><<<AGG_BLOCKS, 256, 0, s0>>>(
        offs, csr, q2, q2 + 128, h2);

    // ---- heads: q3 = h2@[rel3|root3] + [0|b3]; out = agg+root (split) ----
    mm_kernel<64, false, false><<<dim3(MB, 1), 256, 0, s0>>>(
        h2, W3cat, nullptr, b3cat, q3, NN, 128, 64);
    agg_kernel<32, 64, true, false, true><<<AGG_BLOCKS, 256, 0, s0>>>(
        offs, csr, q3, q3 + 32, out);
}

// round 13
// speedup vs baseline: 1.0116x; 1.0116x over previous
#include <cuda_runtime.h>
#include <mma.h>

using namespace nvcuda;

#define NN 50000
#define NE 800000
#define IN_CH 64

// ---------------------------------------------------------------------------
// Scratch layout (single __device__ array). Only [0, ZERO_CNT) is memset per
// launch (flag + degree histogram). All offsets are multiples of 4 floats.
// ---------------------------------------------------------------------------
constexpr size_t OFF_FLAG   = 0;                               // [4] int
constexpr size_t OFF_DEGI   = OFF_FLAG + 4;                    // [NN] int
constexpr size_t ZERO_CNT   = OFF_DEGI + NN;                   // zeroed region end
constexpr size_t OFF_EXCL   = ZERO_CNT;                        // [NN] int
constexpr size_t OFF_BSUM   = OFF_EXCL + NN;                   // [256] int
constexpr size_t OFF_OFFS   = OFF_BSUM + 256;                  // [NN+16] int
constexpr size_t OFF_CURS   = OFF_OFFS + NN + 16;              // [NN] int
constexpr size_t OFF_EIDX   = OFF_CURS + NN;                   // [2*NE] int (src|dst)
constexpr size_t OFF_CSR    = OFF_EIDX + (size_t)2 * NE;       // [NE] int
constexpr size_t OFF_AGGX   = OFF_CSR  + NE;                   // [NN*64] float
constexpr size_t OFF_H1     = OFF_AGGX + (size_t)NN * 64;      // [NN*256]
constexpr size_t OFF_P2     = OFF_H1   + (size_t)NN * 256;     // [NN*128]
constexpr size_t OFF_H2     = OFF_P2   + (size_t)NN * 128;     // [NN*128]
constexpr size_t OFF_P3     = OFF_H2   + (size_t)NN * 128;     // [NN*32]
constexpr size_t OFF_T1     = OFF_P3   + (size_t)NN * 32;      // [NN*256]
constexpr size_t OFF_T2     = OFF_T1   + (size_t)NN * 256;     // [NN*128]
constexpr size_t OFF_T3     = OFF_T2   + (size_t)NN * 128;     // [NN*32]
constexpr size_t OFF_WREL3  = OFF_T3   + (size_t)NN * 32;      // [128*32]
constexpr size_t OFF_WROOT3 = OFF_WREL3 + 128 * 32;            // [128*32]
constexpr size_t OFF_B3     = OFF_WROOT3 + 128 * 32;           // [32]
constexpr size_t TOTAL_F    = OFF_B3 + 32;

__device__ __align__(128) float g_scratch[TOTAL_F];

// ---------------------------------------------------------------------------
// Edge-index dtype detection + conversion (clamped to [0, NN) for safety),
// with the degree histogram fused in (dst-half threads bump degi).
// ---------------------------------------------------------------------------
__global__ void detect_kernel(const unsigned int* __restrict__ raw, int* __restrict__ flag) {
    int t = threadIdx.x;
    unsigned int v = 0;
    for (int i = t; i < 512; i += blockDim.x) v |= raw[2 * i + 1];
    if (__syncthreads_or(v != 0) && t == 0) *flag = 1;
}

__global__ void convert_hist_kernel(const void* __restrict__ raw, const int* __restrict__ flag,
                                    int* __restrict__ eidx, int* __restrict__ degi) {
    int i = blockIdx.x * blockDim.x + threadIdx.x;
    if (i < 2 * NE) {
        int v = (*flag) ? ((const int*)raw)[i]
                        : (int)((const long long*)raw)[i];
        v = min(max(v, 0), NN - 1);
        eidx[i] = v;
        if (i >= NE) atomicAdd(&degi[v], 1);   // dst half -> degree histogram
    }
}

// ---------------------------------------------------------------------------
// CSR construction: exclusive scan (3 small kernels) -> bucket scatter
// ---------------------------------------------------------------------------
__global__ void scan1_kernel(const int* __restrict__ degi, int* __restrict__ excl,
                             int* __restrict__ bsum) {
    __shared__ int sm[256];
    int t = threadIdx.x;
    int i = blockIdx.x * 256 + t;
    int v = (i < NN) ? degi[i] : 0;
    sm[t] = v;
    __syncthreads();
    for (int off = 1; off < 256; off <<= 1) {
        int x = (t >= off) ? sm[t - off] : 0;
        __syncthreads();
        sm[t] += x;
        __syncthreads();
    }
    if (i < NN) excl[i] = sm[t] - v;
    if (t == 255) bsum[blockIdx.x] = sm[255];
}

__global__ void scan2_kernel(int* __restrict__ bsum, int nb) {
    __shared__ int sm[256];
    int t = threadIdx.x;
    int v = (t < nb) ? bsum[t] : 0;
    sm[t] = v;
    __syncthreads();
    for (int off = 1; off < 256; off <<= 1) {
        int x = (t >= off) ? sm[t - off] : 0;
        __syncthreads();
        sm[t] += x;
        __syncthreads();
    }
    if (t < nb) bsum[t] = sm[t] - v;   // exclusive
}

__global__ void scan3_kernel(const int* __restrict__ excl, const int* __restrict__ bsum,
                             int* __restrict__ offs, int* __restrict__ curs) {
    int i = blockIdx.x * blockDim.x + threadIdx.x;
    if (i < NN) {
        int o = excl[i] + bsum[i >> 8];
        offs[i] = o;
        curs[i] = o;
    }
    if (i == 0) offs[NN] = NE;
}

__global__ void csr_build_kernel(const int* __restrict__ esrc, const int* __restrict__ edst,
                                 int* __restrict__ curs, int* __restrict__ csr) {
    int e = blockIdx.x * blockDim.x + threadIdx.x;
    if (e < NE) {
        int p = atomicAdd(&curs[edst[e]], 1);
        csr[p] = esrc[e];
    }
}

// ---------------------------------------------------------------------------
// Segmented mean-aggregation: one warp per destination node, 4-edge unroll.
// OUT[n,:] = f( (1/deg) * sum_{s in N(n)} P[s,:]  [+ T[n,:]] )
// ---------------------------------------------------------------------------
template <int D, bool HAS_ADD, bool RELU, bool SPLIT>
__global__ void agg_kernel(const int* __restrict__ offs, const int* __restrict__ csr,
                           const float* __restrict__ P, const float* __restrict__ T,
                           float* __restrict__ OUT) {
    constexpr int R = D / 32;
    int w = (blockIdx.x * blockDim.x + threadIdx.x) >> 5;
    int lane = threadIdx.x & 31;
    if (w >= NN) return;
    int s = offs[w], e = offs[w + 1];
    float acc[R] = {};
    int i = s;
    for (; i + 3 < e; i += 4) {
        const float* r0 = P + (size_t)csr[i] * D;
        const float* r1 = P + (size_t)csr[i + 1] * D;
        const float* r2 = P + (size_t)csr[i + 2] * D;
        const float* r3 = P + (size_t)csr[i + 3] * D;
#pragma unroll
        for (int r = 0; r < R; r++)
            acc[r] += (__ldg(r0 + lane + 32 * r) + __ldg(r1 + lane + 32 * r))
                    + (__ldg(r2 + lane + 32 * r) + __ldg(r3 + lane + 32 * r));
    }
    for (; i < e; i++) {
        const float* r0 = P + (size_t)csr[i] * D;
#pragma unroll
        for (int r = 0; r < R; r++) acc[r] += __ldg(r0 + lane + 32 * r);
    }
    int deg = e - s;
    float sc = deg > 0 ? 1.0f / (float)deg : 0.0f;
#pragma unroll
    for (int r = 0; r < R; r++) {
        int col = lane + 32 * r;
        float v = acc[r] * sc;
        if (HAS_ADD) v += T[(size_t)w * D + col];
        if (RELU) v = fmaxf(v, 0.f);
        if (SPLIT) {
            float* p = (col < 16) ? (OUT + (size_t)w * 16 + col)
                                  : (OUT + (size_t)NN * 16 + (size_t)w * 16 + (col - 16));
            *p = v;
        } else {
            OUT[(size_t)w * D + col] = v;
        }
    }
}

// ---------------------------------------------------------------------------
// Pack the 4 head weight matrices into concatenated [128,32] buffers
// ---------------------------------------------------------------------------
__global__ void pack3_kernel(const float* __restrict__ Wmu_rel, const float* __restrict__ Wls_rel,
                             const float* __restrict__ Wmu_root, const float* __restrict__ Wls_root,
                             const float* __restrict__ bmu, const float* __restrict__ bls,
                             float* __restrict__ Wrel3, float* __restrict__ Wroot3,
                             float* __restrict__ b3) {
    int i = blockIdx.x * blockDim.x + threadIdx.x;
    if (i < 128 * 32) {
        int k = i / 32, n = i % 32;
        Wrel3[i]  = (n < 16) ? Wmu_rel[k * 16 + n]  : Wls_rel[k * 16 + (n - 16)];
        Wroot3[i] = (n < 16) ? Wmu_root[k * 16 + n] : Wls_root[k * 16 + (n - 16)];
        if (i < 32) b3[i] = (i < 16) ? bmu[i] : bls[i - 16];
    }
}

// ---------------------------------------------------------------------------
// tf32 wmma GEMM with register-prefetch software pipeline.
// 128xBN block tile, BK=16, warps 4 x (BN/32), 32x32 per warp (2x2 frags).
// Next k-tile's global loads are issued BEFORE the current tile's wmma work,
// hiding L2 latency behind tensor compute. tf32 RN convert at smem store
// (numerics identical to the non-pipelined version).
// ---------------------------------------------------------------------------
template <int BN, bool HAS_ADD, bool RELU>
__global__ __launch_bounds__(32 * 4 * (BN / 32))
void mm_kernel(const float* __restrict__ A, const float* __restrict__ W,
               const float* __restrict__ ADD,
               const float* __restrict__ bias, float* __restrict__ OUT,
               int M, int K, int N) {
    constexpr int BM = 128, BK = 16;
    constexpr int WN = BN / 32;
    constexpr int NT = 128 * WN;
    constexpr int LDA = BK + 8;
    constexpr int LDB = BN + 8;
    constexpr int LDC = BN + 8;
    constexpr int AQ = BM * BK / 4 / NT;   // float4 A-loads per thread
    constexpr int BQ = BK * BN / 4 / NT;   // float4 B-loads per thread
    constexpr int SZ_AB = BM * LDA + BK * LDB;
    constexpr int SZ_C  = BM * LDC;
    constexpr int SMEM_FLOATS = SZ_AB > SZ_C ? SZ_AB : SZ_C;
    __shared__ __align__(16) float smem[SMEM_FLOATS];
    float* As = smem;
    float* Bs = smem + BM * LDA;
    float* Cs = smem;

    int t    = threadIdx.x;
    int warp = t >> 5;
    int wm   = warp & 3;
    int wn   = warp >> 2;
    int m0   = blockIdx.x * BM;
    int n0   = blockIdx.y * BN;

    wmma::fragment<wmma::accumulator, 16, 16, 8, float> c[2][2];
#pragma unroll
    for (int i = 0; i < 2; i++)
#pragma unroll
        for (int j = 0; j < 2; j++) wmma::fill_fragment(c[i][j], 0.0f);

    float4 ra[AQ], rb[BQ];

    auto load_tiles = [&](int k0) {
#pragma unroll
        for (int j = 0; j < AQ; j++) {
            int i  = t + j * NT;
            int row = i / (BK / 4);
            int c4  = i % (BK / 4);
            int m = m0 + row;
            ra[j] = (m < M) ? *(const float4*)(A + (size_t)m * K + k0 + c4 * 4)
                            : make_float4(0.f, 0.f, 0.f, 0.f);
        }
#pragma unroll
        for (int j = 0; j < BQ; j++) {
            int i  = t + j * NT;
            int row = i / (BN / 4);
            int c4  = i % (BN / 4);
            rb[j] = *(const float4*)(W + (size_t)(k0 + row) * N + n0 + c4 * 4);
        }
    };
    auto store_tiles = [&]() {
#pragma unroll
        for (int j = 0; j < AQ; j++) {
            int i  = t + j * NT;
            int row = i / (BK / 4);
            int c4  = i % (BK / 4);
            float* d = As + row * LDA + c4 * 4;
            d[0] = wmma::__float_to_tf32(ra[j].x);
            d[1] = wmma::__float_to_tf32(ra[j].y);
            d[2] = wmma::__float_to_tf32(ra[j].z);
            d[3] = wmma::__float_to_tf32(ra[j].w);
        }
#pragma unroll
        for (int j = 0; j < BQ; j++) {
            int i  = t + j * NT;
            int row = i / (BN / 4);
            int c4  = i % (BN / 4);
            float* d = Bs + row * LDB + c4 * 4;
            d[0] = wmma::__float_to_tf32(rb[j].x);
            d[1] = wmma::__float_to_tf32(rb[j].y);
            d[2] = wmma::__float_to_tf32(rb[j].z);
            d[3] = wmma::__float_to_tf32(rb[j].w);
        }
    };

    load_tiles(0);
    for (int k0 = 0; k0 < K; k0 += BK) {
        store_tiles();
        __syncthreads();
        if (k0 + BK < K) load_tiles(k0 + BK);   // prefetch next tile (LDG overlaps wmma)
#pragma unroll
        for (int kk = 0; kk < BK; kk += 8) {
            wmma::fragment<wmma::matrix_a, 16, 16, 8, wmma::precision::tf32, wmma::row_major> a[2];
            wmma::fragment<wmma::matrix_b, 16, 16, 8, wmma::precision::tf32, wmma::row_major> b[2];
#pragma unroll
            for (int i = 0; i < 2; i++)
                wmma::load_matrix_sync(a[i], As + (wm * 32 + i * 16) * LDA + kk, LDA);
#pragma unroll
            for (int j = 0; j < 2; j++)
                wmma::load_matrix_sync(b[j], Bs + kk * LDB + wn * 32 + j * 16, LDB);
#pragma unroll
            for (int i = 0; i < 2; i++)
#pragma unroll
                for (int j = 0; j < 2; j++)
                    wmma::mma_sync(c[i][j], a[i], b[j], c[i][j]);
        }
        __syncthreads();
    }

#pragma unroll
    for (int i = 0; i < 2; i++)
#pragma unroll
        for (int j = 0; j < 2; j++)
            wmma::store_matrix_sync(Cs + (wm * 32 + i * 16) * LDC + wn * 32 + j * 16,
                                    c[i][j], LDC, wmma::mem_row_major);
    __syncthreads();

    for (int i = t; i < BM * BN / 4; i += NT) {
        int row = i / (BN / 4);
        int c4  = i % (BN / 4);
        int m = m0 + row;
        if (m >= M) continue;
        float4 v = *(float4*)(Cs + row * LDC + c4 * 4);
        int n = n0 + c4 * 4;
        if (bias) {
            v.x += bias[n + 0]; v.y += bias[n + 1];
            v.z += bias[n + 2]; v.w += bias[n + 3];
        }
        if (HAS_ADD) {
            const float4 av = *(const float4*)(ADD + (size_t)m * N + n);
            v.x += av.x; v.y += av.y; v.z += av.z; v.w += av.w;
        }
        if (RELU) {
            v.x = fmaxf(v.x, 0.f); v.y = fmaxf(v.y, 0.f);
            v.z = fmaxf(v.z, 0.f); v.w = fmaxf(v.w, 0.f);
        }
        *(float4*)(OUT + (size_t)m * N + n) = v;
    }
}

// ---------------------------------------------------------------------------
// Launch: two-stream fork/join (round-10 topology). Stream 0 (capture stream)
// runs the edge path; s2 runs the root-path GEMMs overlapped with it.
// ---------------------------------------------------------------------------
extern "C" void kernel_launch(void* const* d_in, const int* in_sizes, int n_in,
                              void* d_out, int out_size) {
    const float *x, *W1_rel, *b1, *W1_root, *W2_rel, *b2, *W2_root;
    const float *Wmu_rel, *bmu, *Wmu_root, *Wls_rel, *bls, *Wls_root;
    const void* ei_raw;

    if (in_sizes[0] == NN * IN_CH) {
        // dict order
        x        = (const float*)d_in[0];
        W1_rel   = (const float*)d_in[1];
        b1       = (const float*)d_in[2];
        W1_root  = (const float*)d_in[3];
        W2_rel   = (const float*)d_in[4];
        b2       = (const float*)d_in[5];
        W2_root  = (const float*)d_in[6];
        Wmu_rel  = (const float*)d_in[7];
        bmu      = (const float*)d_in[8];
        Wmu_root = (const float*)d_in[9];
        Wls_rel  = (const float*)d_in[10];
        bls      = (const float*)d_in[11];
        Wls_root = (const float*)d_in[12];
        ei_raw   = d_in[13];
    } else {
        // alphabetical order
        W1_rel   = (const float*)d_in[0];
        W1_root  = (const float*)d_in[1];
        W2_rel   = (const float*)d_in[2];
        W2_root  = (const float*)d_in[3];
        Wls_rel  = (const float*)d_in[4];
        Wls_root = (const float*)d_in[5];
        Wmu_rel  = (const float*)d_in[6];
        Wmu_root = (const float*)d_in[7];
        b1       = (const float*)d_in[8];
        b2       = (const float*)d_in[9];
        bls      = (const float*)d_in[10];
        bmu      = (const float*)d_in[11];
        ei_raw   = d_in[12];
        x        = (const float*)d_in[13];
    }
    float* out = (float*)d_out;

    float* base = nullptr;
    cudaGetSymbolAddress((void**)&base, g_scratch);
    int*   flag   = (int*)(base + OFF_FLAG);
    int*   degi   = (int*)(base + OFF_DEGI);
    int*   excl   = (int*)(base + OFF_EXCL);
    int*   bsum   = (int*)(base + OFF_BSUM);
    int*   offs   = (int*)(base + OFF_OFFS);
    int*   curs   = (int*)(base + OFF_CURS);
    int*   eidx   = (int*)(base + OFF_EIDX);
    int*   csr    = (int*)(base + OFF_CSR);
    int*   esrc   = eidx;
    int*   edst   = eidx + NE;
    float* aggx   = base + OFF_AGGX;
    float* h1     = base + OFF_H1;
    float* p2     = base + OFF_P2;
    float* h2     = base + OFF_H2;
    float* p3     = base + OFF_P3;
    float* t1     = base + OFF_T1;
    float* t2     = base + OFF_T2;
    float* t3     = base + OFF_T3;
    float* Wrel3  = base + OFF_WREL3;
    float* Wroot3 = base + OFF_WROOT3;
    float* b3     = base + OFF_B3;

    // One-time stream/event creation (outside capture on the correctness run;
    // reused identically on every call -> deterministic work).
    static cudaStream_t s2 = nullptr;
    static cudaEvent_t evRoot, evT1, evH1, evT2, evH2, evT3;
    if (!s2) {
        cudaStreamCreateWithFlags(&s2, cudaStreamNonBlocking);
        cudaEventCreateWithFlags(&evRoot, cudaEventDisableTiming);
        cudaEventCreateWithFlags(&evT1, cudaEventDisableTiming);
        cudaEventCreateWithFlags(&evH1, cudaEventDisableTiming);
        cudaEventCreateWithFlags(&evT2, cudaEventDisableTiming);
        cudaEventCreateWithFlags(&evH2, cudaEventDisableTiming);
        cudaEventCreateWithFlags(&evT3, cudaEventDisableTiming);
    }
    cudaStream_t s0 = 0;

    const int MB = (NN + 127) / 128;     // 391
    const int AGG_BLOCKS = (NN + 7) / 8; // 8 warps/block
    const int NB = (NN + 255) / 256;     // 196

    // fork s2 off the capture stream
    cudaEventRecord(evRoot, s0);
    cudaStreamWaitEvent(s2, evRoot, 0);

    // ---- s2: root path prologue (independent of edges) ----
    pack3_kernel<<<(128 * 32 + 255) / 256, 256, 0, s2>>>(
        Wmu_rel, Wls_rel, Wmu_root, Wls_root, bmu, bls, Wrel3, Wroot3, b3);
    mm_kernel<64, false, false><<<dim3(MB, 4), 256, 0, s2>>>(
        x, W1_root, nullptr, b1, t1, NN, 64, 256);                 // t1 = x@W1_root + b1
    cudaEventRecord(evT1, s2);

    // ---- s0: edge path (CSR build + aggx) ----
    cudaMemsetAsync(base, 0, ZERO_CNT * sizeof(float), s0);
    detect_kernel<<<1, 256, 0, s0>>>((const unsigned int*)ei_raw, flag);
    convert_hist_kernel<<<(2 * NE + 255) / 256, 256, 0, s0>>>(ei_raw, flag, eidx, degi);
    scan1_kernel<<<NB, 256, 0, s0>>>(degi, excl, bsum);
    scan2_kernel<<<1, 256, 0, s0>>>(bsum, NB);
    scan3_kernel<<<NB, 256, 0, s0>>>(excl, bsum, offs, curs);
    csr_build_kernel<<<(NE + 255) / 256, 256, 0, s0>>>(esrc, edst, curs, csr);
    agg_kernel<64, false, false, false><<<AGG_BLOCKS, 256, 0, s0>>>(
        offs, csr, x, nullptr, aggx);

    // ---- layer 1 combine: h1 = relu(aggx@W1_rel + t1) ----
    cudaStreamWaitEvent(s0, evT1, 0);
    mm_kernel<64, true, true><<<dim3(MB, 4), 256, 0, s0>>>(
        aggx, W1_rel, t1, nullptr, h1, NN, 64, 256);
    cudaEventRecord(evH1, s0);

    // ---- s2: t2 = h1@W2_root + b2 (overlaps p2 projection on s0) ----
    cudaStreamWaitEvent(s2, evH1, 0);
    mm_kernel<64, false, false><<<dim3(MB, 2), 256, 0, s2>>>(
        h1, W2_root, nullptr, b2, t2, NN, 256, 128);
    cudaEventRecord(evT2, s2);

    // ---- s0: p2 = h1@W2_rel; h2 = relu(agg(p2) + t2) ----
    mm_kernel<64, false, false><<<dim3(MB, 2), 256, 0, s0>>>(
        h1, W2_rel, nullptr, nullptr, p2, NN, 256, 128);
    cudaStreamWaitEvent(s0, evT2, 0);
    agg_kernel<128, true, true, false><<<AGG_BLOCKS, 256, 0, s0>>>(
        offs, csr, p2, t2, h2);
    cudaEventRecord(evH2, s0);

    // ---- s2: t3 = h2@Wroot3 + b3 (overlaps p3 projection on s0) ----
    cudaStreamWaitEvent(s2, evH2, 0);
    mm_kernel<32, false, false><<<dim3(MB, 1), 128, 0, s2>>>(
        h2, Wroot3, nullptr, b3, t3, NN, 128, 32);
    cudaEventRecord(evT3, s2);

    // ---- s0: p3 = h2@Wrel3; out = agg(p3) + t3 (split mu/logstd) ----
    mm_kernel<32, false, false><<<dim3(MB, 1), 128, 0, s0>>>(
        h2, Wrel3, nullptr, nullptr, p3, NN, 128, 32);
    cudaStreamWaitEvent(s0, evT3, 0);
    agg_kernel<32, true, false, true><<<AGG_BLOCKS, 256, 0, s0>>>(
        offs, csr, p3, t3, out);
}

// round 14
// speedup vs baseline: 1.0233x; 1.0116x over previous
#include <cuda_runtime.h>
#include <mma.h>

using namespace nvcuda;

#define NN 50000
#define NE 800000
#define IN_CH 64

// ---------------------------------------------------------------------------
// Scratch layout (single __device__ array). Only [0, ZERO_CNT) is memset per
// launch (flag + degree histogram). All offsets are multiples of 4 floats.
// ---------------------------------------------------------------------------
constexpr size_t OFF_FLAG   = 0;                               // [4] int
constexpr size_t OFF_DEGI   = OFF_FLAG + 4;                    // [NN] int
constexpr size_t ZERO_CNT   = OFF_DEGI + NN;                   // zeroed region end
constexpr size_t OFF_EXCL   = ZERO_CNT;                        // [NN] int
constexpr size_t OFF_BSUM   = OFF_EXCL + NN;                   // [256] int
constexpr size_t OFF_OFFS   = OFF_BSUM + 256;                  // [NN+16] int
constexpr size_t OFF_CURS   = OFF_OFFS + NN + 16;              // [NN] int
constexpr size_t OFF_CSR    = OFF_CURS + NN;                   // [NE] int
constexpr size_t OFF_AGGX   = OFF_CSR  + NE;                   // [NN*64] float
constexpr size_t OFF_H1     = OFF_AGGX + (size_t)NN * 64;      // [NN*256]
constexpr size_t OFF_P2     = OFF_H1   + (size_t)NN * 256;     // [NN*128]
constexpr size_t OFF_H2     = OFF_P2   + (size_t)NN * 128;     // [NN*128]
constexpr size_t OFF_P3     = OFF_H2   + (size_t)NN * 128;     // [NN*32]
constexpr size_t OFF_T1     = OFF_P3   + (size_t)NN * 32;      // [NN*256]
constexpr size_t OFF_T2     = OFF_T1   + (size_t)NN * 256;     // [NN*128]
constexpr size_t OFF_T3     = OFF_T2   + (size_t)NN * 128;     // [NN*32]
constexpr size_t OFF_WREL3  = OFF_T3   + (size_t)NN * 32;      // [128*32]
constexpr size_t OFF_WROOT3 = OFF_WREL3 + 128 * 32;            // [128*32]
constexpr size_t OFF_B3     = OFF_WROOT3 + 128 * 32;           // [32]
constexpr size_t TOTAL_F    = OFF_B3 + 32;

__device__ __align__(128) float g_scratch[TOTAL_F];

// ---------------------------------------------------------------------------
// Edge-index dtype detection. int64 little-endian with values < 50000 =>
// every odd 32-bit word is 0; int32 => odd words are nonzero src indices.
// ---------------------------------------------------------------------------
__global__ void detect_kernel(const unsigned int* __restrict__ raw, int* __restrict__ flag) {
    int t = threadIdx.x;
    unsigned int v = 0;
    for (int i = t; i < 512; i += blockDim.x) v |= raw[2 * i + 1];
    if (__syncthreads_or(v != 0) && t == 0) *flag = 1;
}

__device__ __forceinline__ int load_edge(const void* raw, int f, size_t idx) {
    int v = f ? ((const int*)raw)[idx] : (int)((const long long*)raw)[idx];
    return min(max(v, 0), NN - 1);
}

// ---------------------------------------------------------------------------
// CSR construction directly from the raw edge tensor (no eidx staging):
// histogram -> exclusive scan (3 small kernels) -> bucket scatter.
// ---------------------------------------------------------------------------
__global__ void hist_kernel(const void* __restrict__ raw, const int* __restrict__ flag,
                            int* __restrict__ degi) {
    int e = blockIdx.x * blockDim.x + threadIdx.x;
    if (e < NE) {
        int dst = load_edge(raw, *flag, (size_t)NE + e);
        atomicAdd(&degi[dst], 1);
    }
}

__global__ void scan1_kernel(const int* __restrict__ degi, int* __restrict__ excl,
                             int* __restrict__ bsum) {
    __shared__ int sm[256];
    int t = threadIdx.x;
    int i = blockIdx.x * 256 + t;
    int v = (i < NN) ? degi[i] : 0;
    sm[t] = v;
    __syncthreads();
    for (int off = 1; off < 256; off <<= 1) {
        int x = (t >= off) ? sm[t - off] : 0;
        __syncthreads();
        sm[t] += x;
        __syncthreads();
    }
    if (i < NN) excl[i] = sm[t] - v;
    if (t == 255) bsum[blockIdx.x] = sm[255];
}

__global__ void scan2_kernel(int* __restrict__ bsum, int nb) {
    __shared__ int sm[256];
    int t = threadIdx.x;
    int v = (t < nb) ? bsum[t] : 0;
    sm[t] = v;
    __syncthreads();
    for (int off = 1; off < 256; off <<= 1) {
        int x = (t >= off) ? sm[t - off] : 0;
        __syncthreads();
        sm[t] += x;
        __syncthreads();
    }
    if (t < nb) bsum[t] = sm[t] - v;   // exclusive
}

__global__ void scan3_kernel(const int* __restrict__ excl, const int* __restrict__ bsum,
                             int* __restrict__ offs, int* __restrict__ curs) {
    int i = blockIdx.x * blockDim.x + threadIdx.x;
    if (i < NN) {
        int o = excl[i] + bsum[i >> 8];
        offs[i] = o;
        curs[i] = o;
    }
    if (i == 0) offs[NN] = NE;
}

__global__ void csr_build_kernel(const void* __restrict__ raw, const int* __restrict__ flag,
                                 int* __restrict__ curs, int* __restrict__ csr) {
    int e = blockIdx.x * blockDim.x + threadIdx.x;
    if (e < NE) {
        int f = *flag;
        int src = load_edge(raw, f, e);
        int dst = load_edge(raw, f, (size_t)NE + e);
        int p = atomicAdd(&curs[dst], 1);
        csr[p] = src;
    }
}

// ---------------------------------------------------------------------------
// Segmented mean-aggregation: one warp per destination node, 4-row unroll,
// VECTORIZED: each lane covers V = D/32 consecutive columns (float/2/4),
// cutting LDG issue count 4x for D=128 vs stride-32 scalars.
// OUT[n,:] = f( (1/deg) * sum_{s in N(n)} P[s,:]  [+ T[n,:]] )
// ---------------------------------------------------------------------------
template <int D, bool HAS_ADD, bool RELU, bool SPLIT>
__global__ void agg_kernel(const int* __restrict__ offs, const int* __restrict__ csr,
                           const float* __restrict__ P, const float* __restrict__ T,
                           float* __restrict__ OUT) {
    constexpr int V = D / 32;            // floats per lane (1, 2, or 4)
    int w = (blockIdx.x * blockDim.x + threadIdx.x) >> 5;
    int lane = threadIdx.x & 31;
    if (w >= NN) return;
    int s = offs[w], e = offs[w + 1];
    int cb = lane * V;                   // this lane's column base
    float acc[V] = {};

    auto add_row = [&](const float* r) {
        if constexpr (V == 4) {
            float4 v = __ldg((const float4*)(r + cb));
            acc[0] += v.x; acc[1] += v.y; acc[2] += v.z; acc[3] += v.w;
        } else if constexpr (V == 2) {
            float2 v = __ldg((const float2*)(r + cb));
            acc[0] += v.x; acc[1] += v.y;
        } else {
            acc[0] += __ldg(r + cb);
        }
    };

    int i = s;
    for (; i + 3 < e; i += 4) {
        const float* r0 = P + (size_t)csr[i] * D;
        const float* r1 = P + (size_t)csr[i + 1] * D;
        const float* r2 = P + (size_t)csr[i + 2] * D;
        const float* r3 = P + (size_t)csr[i + 3] * D;
        add_row(r0); add_row(r1); add_row(r2); add_row(r3);
    }
    for (; i < e; i++) add_row(P + (size_t)csr[i] * D);

    int deg = e - s;
    float sc = deg > 0 ? 1.0f / (float)deg : 0.0f;
#pragma unroll
    for (int r = 0; r < V; r++) {
        acc[r] *= sc;
        if (HAS_ADD) acc[r] += T[(size_t)w * D + cb + r];
        if (RELU) acc[r] = fmaxf(acc[r], 0.f);
    }
    if (SPLIT) {
        // D = 32, V = 1: cols [0,16) -> mu, [16,32) -> logstd
        int col = cb;
        float* p = (col < 16) ? (OUT + (size_t)w * 16 + col)
                              : (OUT + (size_t)NN * 16 + (size_t)w * 16 + (col - 16));
        *p = acc[0];
    } else if constexpr (V == 4) {
        *(float4*)(OUT + (size_t)w * D + cb) = make_float4(acc[0], acc[1], acc[2], acc[3]);
    } else if constexpr (V == 2) {
        *(float2*)(OUT + (size_t)w * D + cb) = make_float2(acc[0], acc[1]);
    } else {
        OUT[(size_t)w * D + cb] = acc[0];
    }
}

// ---------------------------------------------------------------------------
// Pack the 4 head weight matrices into concatenated [128,32] buffers
// ---------------------------------------------------------------------------
__global__ void pack3_kernel(const float* __restrict__ Wmu_rel, const float* __restrict__ Wls_rel,
                             const float* __restrict__ Wmu_root, const float* __restrict__ Wls_root,
                             const float* __restrict__ bmu, const float* __restrict__ bls,
                             float* __restrict__ Wrel3, float* __restrict__ Wroot3,
                             float* __restrict__ b3) {
    int i = blockIdx.x * blockDim.x + threadIdx.x;
    if (i < 128 * 32) {
        int k = i / 32, n = i % 32;
        Wrel3[i]  = (n < 16) ? Wmu_rel[k * 16 + n]  : Wls_rel[k * 16 + (n - 16)];
        Wroot3[i] = (n < 16) ? Wmu_root[k * 16 + n] : Wls_root[k * 16 + (n - 16)];
        if (i < 32) b3[i] = (i < 16) ? bmu[i] : bls[i - 16];
    }
}

// ---------------------------------------------------------------------------
// tf32 wmma GEMM with register-prefetch software pipeline (round-13, neutral
// but numerics-identical and kept). 128xBN tile, BK=16, 32x32 per warp.
// ---------------------------------------------------------------------------
template <int BN, bool HAS_ADD, bool RELU>
__global__ __launch_bounds__(32 * 4 * (BN / 32))
void mm_kernel(const float* __restrict__ A, const float* __restrict__ W,
               const float* __restrict__ ADD,
               const float* __restrict__ bias, float* __restrict__ OUT,
               int M, int K, int N) {
    constexpr int BM = 128, BK = 16;
    constexpr int WN = BN / 32;
    constexpr int NT = 128 * WN;
    constexpr int LDA = BK + 8;
    constexpr int LDB = BN + 8;
    constexpr int LDC = BN + 8;
    constexpr int AQ = BM * BK / 4 / NT;
    constexpr int BQ = BK * BN / 4 / NT;
    constexpr int SZ_AB = BM * LDA + BK * LDB;
    constexpr int SZ_C  = BM * LDC;
    constexpr int SMEM_FLOATS = SZ_AB > SZ_C ? SZ_AB : SZ_C;
    __shared__ __align__(16) float smem[SMEM_FLOATS];
    float* As = smem;
    float* Bs = smem + BM * LDA;
    float* Cs = smem;

    int t    = threadIdx.x;
    int warp = t >> 5;
    int wm   = warp & 3;
    int wn   = warp >> 2;
    int m0   = blockIdx.x * BM;
    int n0   = blockIdx.y * BN;

    wmma::fragment<wmma::accumulator, 16, 16, 8, float> c[2][2];
#pragma unroll
    for (int i = 0; i < 2; i++)
#pragma unroll
        for (int j = 0; j < 2; j++) wmma::fill_fragment(c[i][j], 0.0f);

    float4 ra[AQ], rb[BQ];

    auto load_tiles = [&](int k0) {
#pragma unroll
        for (int j = 0; j < AQ; j++) {
            int i  = t + j * NT;
            int row = i / (BK / 4);
            int c4  = i % (BK / 4);
            int m = m0 + row;
            ra[j] = (m < M) ? *(const float4*)(A + (size_t)m * K + k0 + c4 * 4)
                            : make_float4(0.f, 0.f, 0.f, 0.f);
        }
#pragma unroll
        for (int j = 0; j < BQ; j++) {
            int i  = t + j * NT;
            int row = i / (BN / 4);
            int c4  = i % (BN / 4);
            rb[j] = *(const float4*)(W + (size_t)(k0 + row) * N + n0 + c4 * 4);
        }
    };
    auto store_tiles = [&]() {
#pragma unroll
        for (int j = 0; j < AQ; j++) {
            int i  = t + j * NT;
            int row = i / (BK / 4);
            int c4  = i % (BK / 4);
            float* d = As + row * LDA + c4 * 4;
            d[0] = wmma::__float_to_tf32(ra[j].x);
            d[1] = wmma::__float_to_tf32(ra[j].y);
            d[2] = wmma::__float_to_tf32(ra[j].z);
            d[3] = wmma::__float_to_tf32(ra[j].w);
        }
#pragma unroll
        for (int j = 0; j < BQ; j++) {
            int i  = t + j * NT;
            int row = i / (BN / 4);
            int c4  = i % (BN / 4);
            float* d = Bs + row * LDB + c4 * 4;
            d[0] = wmma::__float_to_tf32(rb[j].x);
            d[1] = wmma::__float_to_tf32(rb[j].y);
            d[2] = wmma::__float_to_tf32(rb[j].z);
            d[3] = wmma::__float_to_tf32(rb[j].w);
        }
    };

    load_tiles(0);
    for (int k0 = 0; k0 < K; k0 += BK) {
        store_tiles();
        __syncthreads();
        if (k0 + BK < K) load_tiles(k0 + BK);
#pragma unroll
        for (int kk = 0; kk < BK; kk += 8) {
            wmma::fragment<wmma::matrix_a, 16, 16, 8, wmma::precision::tf32, wmma::row_major> a[2];
            wmma::fragment<wmma::matrix_b, 16, 16, 8, wmma::precision::tf32, wmma::row_major> b[2];
#pragma unroll
            for (int i = 0; i < 2; i++)
                wmma::load_matrix_sync(a[i], As + (wm * 32 + i * 16) * LDA + kk, LDA);
#pragma unroll
            for (int j = 0; j < 2; j++)
                wmma::load_matrix_sync(b[j], Bs + kk * LDB + wn * 32 + j * 16, LDB);
#pragma unroll
            for (int i = 0; i < 2; i++)
#pragma unroll
                for (int j = 0; j < 2; j++)
                    wmma::mma_sync(c[i][j], a[i], b[j], c[i][j]);
        }
        __syncthreads();
    }

#pragma unroll
    for (int i = 0; i < 2; i++)
#pragma unroll
        for (int j = 0; j < 2; j++)
            wmma::store_matrix_sync(Cs + (wm * 32 + i * 16) * LDC + wn * 32 + j * 16,
                                    c[i][j], LDC, wmma::mem_row_major);
    __syncthreads();

    for (int i = t; i < BM * BN / 4; i += NT) {
        int row = i / (BN / 4);
        int c4  = i % (BN / 4);
        int m = m0 + row;
        if (m >= M) continue;
        float4 v = *(float4*)(Cs + row * LDC + c4 * 4);
        int n = n0 + c4 * 4;
        if (bias) {
            v.x += bias[n + 0]; v.y += bias[n + 1];
            v.z += bias[n + 2]; v.w += bias[n + 3];
        }
        if (HAS_ADD) {
            const float4 av = *(const float4*)(ADD + (size_t)m * N + n);
            v.x += av.x; v.y += av.y; v.z += av.z; v.w += av.w;
        }
        if (RELU) {
            v.x = fmaxf(v.x, 0.f); v.y = fmaxf(v.y, 0.f);
            v.z = fmaxf(v.z, 0.f); v.w = fmaxf(v.w, 0.f);
        }
        *(float4*)(OUT + (size_t)m * N + n) = v;
    }
}

// ---------------------------------------------------------------------------
// Launch: two-stream fork/join (round-10 topology). Stream 0 (capture stream)
// runs the edge path; s2 runs the root-path GEMMs overlapped with it.
// ---------------------------------------------------------------------------
extern "C" void kernel_launch(void* const* d_in, const int* in_sizes, int n_in,
                              void* d_out, int out_size) {
    const float *x, *W1_rel, *b1, *W1_root, *W2_rel, *b2, *W2_root;
    const float *Wmu_rel, *bmu, *Wmu_root, *Wls_rel, *bls, *Wls_root;
    const void* ei_raw;

    if (in_sizes[0] == NN * IN_CH) {
        // dict order
        x        = (const float*)d_in[0];
        W1_rel   = (const float*)d_in[1];
        b1       = (const float*)d_in[2];
        W1_root  = (const float*)d_in[3];
        W2_rel   = (const float*)d_in[4];
        b2       = (const float*)d_in[5];
        W2_root  = (const float*)d_in[6];
        Wmu_rel  = (const float*)d_in[7];
        bmu      = (const float*)d_in[8];
        Wmu_root = (const float*)d_in[9];
        Wls_rel  = (const float*)d_in[10];
        bls      = (const float*)d_in[11];
        Wls_root = (const float*)d_in[12];
        ei_raw   = d_in[13];
    } else {
        // alphabetical order
        W1_rel   = (const float*)d_in[0];
        W1_root  = (const float*)d_in[1];
        W2_rel   = (const float*)d_in[2];
        W2_root  = (const float*)d_in[3];
        Wls_rel  = (const float*)d_in[4];
        Wls_root = (const float*)d_in[5];
        Wmu_rel  = (const float*)d_in[6];
        Wmu_root = (const float*)d_in[7];
        b1       = (const float*)d_in[8];
        b2       = (const float*)d_in[9];
        bls      = (const float*)d_in[10];
        bmu      = (const float*)d_in[11];
        ei_raw   = d_in[12];
        x        = (const float*)d_in[13];
    }
    float* out = (float*)d_out;

    float* base = nullptr;
    cudaGetSymbolAddress((void**)&base, g_scratch);
    int*   flag   = (int*)(base + OFF_FLAG);
    int*   degi   = (int*)(base + OFF_DEGI);
    int*   excl   = (int*)(base + OFF_EXCL);
    int*   bsum   = (int*)(base + OFF_BSUM);
    int*   offs   = (int*)(base + OFF_OFFS);
    int*   curs   = (int*)(base + OFF_CURS);
    int*   csr    = (int*)(base + OFF_CSR);
    float* aggx   = base + OFF_AGGX;
    float* h1     = base + OFF_H1;
    float* p2     = base + OFF_P2;
    float* h2     = base + OFF_H2;
    float* p3     = base + OFF_P3;
    float* t1     = base + OFF_T1;
    float* t2     = base + OFF_T2;
    float* t3     = base + OFF_T3;
    float* Wrel3  = base + OFF_WREL3;
    float* Wroot3 = base + OFF_WROOT3;
    float* b3     = base + OFF_B3;

    // One-time stream/event creation (outside capture on the correctness run;
    // reused identically on every call -> deterministic work).
    static cudaStream_t s2 = nullptr;
    static cudaEvent_t evRoot, evT1, evH1, evT2, evH2, evT3;
    if (!s2) {
        cudaStreamCreateWithFlags(&s2, cudaStreamNonBlocking);
        cudaEventCreateWithFlags(&evRoot, cudaEventDisableTiming);
        cudaEventCreateWithFlags(&evT1, cudaEventDisableTiming);
        cudaEventCreateWithFlags(&evH1, cudaEventDisableTiming);
        cudaEventCreateWithFlags(&evT2, cudaEventDisableTiming);
        cudaEventCreateWithFlags(&evH2, cudaEventDisableTiming);
        cudaEventCreateWithFlags(&evT3, cudaEventDisableTiming);
    }
    cudaStream_t s0 = 0;

    const int MB = (NN + 127) / 128;     // 391
    const int AGG_BLOCKS = (NN + 7) / 8; // 8 warps/block
    const int NB = (NN + 255) / 256;     // 196

    // fork s2 off the capture stream
    cudaEventRecord(evRoot, s0);
    cudaStreamWaitEvent(s2, evRoot, 0);

    // ---- s2: root path prologue (independent of edges) ----
    pack3_kernel<<<(128 * 32 + 255) / 256, 256, 0, s2>>>(
        Wmu_rel, Wls_rel, Wmu_root, Wls_root, bmu, bls, Wrel3, Wroot3, b3);
    mm_kernel<64, false, false><<<dim3(MB, 4), 256, 0, s2>>>(
        x, W1_root, nullptr, b1, t1, NN, 64, 256);                 // t1 = x@W1_root + b1
    cudaEventRecord(evT1, s2);

    // ---- s0: edge path (CSR build + aggx) ----
    cudaMemsetAsync(base, 0, ZERO_CNT * sizeof(float), s0);
    detect_kernel<<<1, 256, 0, s0>>>((const unsigned int*)ei_raw, flag);
    hist_kernel<<<(NE + 255) / 256, 256, 0, s0>>>(ei_raw, flag, degi);
    scan1_kernel<<<NB, 256, 0, s0>>>(degi, excl, bsum);
    scan2_kernel<<<1, 256, 0, s0>>>(bsum, NB);
    scan3_kernel<<<NB, 256, 0, s0>>>(excl, bsum, offs, curs);
    csr_build_kernel<<<(NE + 255) / 256, 256, 0, s0>>>(ei_raw, flag, curs, csr);
    agg_kernel<64, false, false, false><<<AGG_BLOCKS, 256, 0, s0>>>(
        offs, csr, x, nullptr, aggx);

    // ---- layer 1 combine: h1 = relu(aggx@W1_rel + t1) ----
    cudaStreamWaitEvent(s0, evT1, 0);
    mm_kernel<64, true, true><<<dim3(MB, 4), 256, 0, s0>>>(
        aggx, W1_rel, t1, nullptr, h1, NN, 64, 256);
    cudaEventRecord(evH1, s0);

    // ---- s2: t2 = h1@W2_root + b2 (overlaps p2 projection on s0) ----
    cudaStreamWaitEvent(s2, evH1, 0);
    mm_kernel<64, false, false><<<dim3(MB, 2), 256, 0, s2>>>(
        h1, W2_root, nullptr, b2, t2, NN, 256, 128);
    cudaEventRecord(evT2, s2);

    // ---- s0: p2 = h1@W2_rel; h2 = relu(agg(p2) + t2) ----
    mm_kernel<64, false, false><<<dim3(MB, 2), 256, 0, s0>>>(
        h1, W2_rel, nullptr, nullptr, p2, NN, 256, 128);
    cudaStreamWaitEvent(s0, evT2, 0);
    agg_kernel<128, true, true, false><<<AGG_BLOCKS, 256, 0, s0>>>(
        offs, csr, p2, t2, h2);
    cudaEventRecord(evH2, s0);

    // ---- s2: t3 = h2@Wroot3 + b3 (overlaps p3 projection on s0) ----
    cudaStreamWaitEvent(s2, evH2, 0);
    mm_kernel<32, false, false><<<dim3(MB, 1), 128, 0, s2>>>(
        h2, Wroot3, nullptr, b3, t3, NN, 128, 32);
    cudaEventRecord(evT3, s2);

    // ---- s0: p3 = h2@Wrel3; out = agg(p3) + t3 (split mu/logstd) ----
    mm_kernel<32, false, false><<<dim3(MB, 1), 128, 0, s0>>>(
        h2, Wrel3, nullptr, nullptr, p3, NN, 128, 32);
    cudaStreamWaitEvent(s0, evT3, 0);
    agg_kernel<32, true, false, true><<<AGG_BLOCKS, 256, 0, s0>>>(
        offs, csr, p3, t3, out);
}